// round 14
// baseline (speedup 1.0000x reference)
#include <cuda_runtime.h>

typedef unsigned long long ull;

#define SEQ_T 512
#define NB    64
#define NIN   256
#define NH    512
#define NROW  2048                    // 4 gates * NH rows
#define NCOL  32768                   // SEQ_T * NB
#define NCTA  128                     // 32 j-groups x 4 b-groups
#define NTHR  256
#define HSEQ_ELEMS (512L*64*512)      // 16777216
// lstm smem: U2 (512k x 33 f2) 135168B + h2 (512k x 17 f2) 69632B
#define LSTM_SMEM (135168 + 69632)

// ---------------- device scratch (static: no allocations allowed) ----------
__device__ float    g_xp[(long)NROW * NCOL];   // [gate*512+j][t*64+b]
__device__ float    g_hbuf[2][NH * NB];        // [j][b] layout, double buffered
__device__ float    g_bias[NROW];              // Wb + Ub folded
__device__ unsigned g_bar[SEQ_T * 4];          // per-(step, b-group) barrier slots

// ---------------- f32x2 helpers (packed FFMA2 = 2x fp32 throughput) --------
__device__ __forceinline__ void fma2(ull &d, ull a, ull b){
    asm("fma.rn.f32x2 %0, %1, %2, %0;" : "+l"(d) : "l"(a), "l"(b));
}
__device__ __forceinline__ ull dup2(float v){
    ull r; asm("mov.b64 %0, {%1, %1};" : "=l"(r) : "f"(v)); return r;
}
__device__ __forceinline__ float2 unpack2(ull v){
    float2 r; asm("mov.b64 {%0, %1}, %2;" : "=f"(r.x), "=f"(r.y) : "l"(v)); return r;
}
// fast sigmoid / tanh via MUFU (__expf + __fdividef); exact limits at +-inf.
// Validated: rel_err 2.8e-7 (threshold 1e-3).
__device__ __forceinline__ float fsig(float x){
    return __fdividef(1.f, 1.f + __expf(-x));
}
__device__ __forceinline__ float ftanh(float x){
    return 1.f - __fdividef(2.f, __expf(2.f * x) + 1.f);
}

// ---------------- init: h0 -> hbuf[0] ([j][b]), fold biases, zero barriers -
__global__ void init_kernel(const float* __restrict__ h0,
    const float* __restrict__ Wfb, const float* __restrict__ Ufb,
    const float* __restrict__ Wib, const float* __restrict__ Uib,
    const float* __restrict__ Wob, const float* __restrict__ Uob,
    const float* __restrict__ Wcb, const float* __restrict__ Ucb)
{
    int i = blockIdx.x * blockDim.x + threadIdx.x;   // 0..32767
    int j = i >> 6, b = i & 63;
    g_hbuf[0][i] = h0[b * NH + j];                   // transpose to [j][b]
    if (i < NROW) {
        int g = i >> 9, jj = i & 511;
        const float* Wb = (g==0)?Wfb:(g==1)?Wib:(g==2)?Wob:Wcb;
        const float* Ub = (g==0)?Ufb:(g==1)?Uib:(g==2)?Uob:Ucb;
        g_bias[i] = Wb[jj] + Ub[jj];
    }
    if (i < SEQ_T * 4) g_bar[i] = 0u;
}

// ---------------- phase 1: xp = W @ x^T + (Wb+Ub), all 4 gates -------------
__global__ __launch_bounds__(256) void gemm_xw(
    const float* __restrict__ x,
    const float* __restrict__ Wf, const float* __restrict__ Wi,
    const float* __restrict__ Wo, const float* __restrict__ Wc)
{
    __shared__ float As[16 * 128];
    __shared__ float Bs[16 * 128];
    const int tid = threadIdx.x;
    const int bx = blockIdx.x, by = blockIdx.y;
    const int g = (by * 128) >> 9;
    const float* Wg = (g==0)?Wf:(g==1)?Wi:(g==2)?Wo:Wc;
    const int rowA0 = (by * 128) & 511;
    const int tx = tid & 15, ty = tid >> 4;
    const int lr = tid >> 2;
    const int lk4 = (tid & 3) * 4;

    ull acc[4][8];
    #pragma unroll
    for (int m = 0; m < 4; m++)
        #pragma unroll
        for (int n = 0; n < 8; n++) acc[m][n] = 0ull;

    for (int kt = 0; kt < NIN; kt += 16) {
        float4 a0 = __ldg((const float4*)&Wg[(rowA0 + lr)      * NIN + kt + lk4]);
        float4 a1 = __ldg((const float4*)&Wg[(rowA0 + lr + 64) * NIN + kt + lk4]);
        float4 b0 = __ldg((const float4*)&x[((long)bx*128 + lr)      * NIN + kt + lk4]);
        float4 b1 = __ldg((const float4*)&x[((long)bx*128 + lr + 64) * NIN + kt + lk4]);
        __syncthreads();
        As[(lk4+0)*128 + lr] = a0.x; As[(lk4+1)*128 + lr] = a0.y;
        As[(lk4+2)*128 + lr] = a0.z; As[(lk4+3)*128 + lr] = a0.w;
        As[(lk4+0)*128 + lr+64] = a1.x; As[(lk4+1)*128 + lr+64] = a1.y;
        As[(lk4+2)*128 + lr+64] = a1.z; As[(lk4+3)*128 + lr+64] = a1.w;
        Bs[(lk4+0)*128 + lr] = b0.x; Bs[(lk4+1)*128 + lr] = b0.y;
        Bs[(lk4+2)*128 + lr] = b0.z; Bs[(lk4+3)*128 + lr] = b0.w;
        Bs[(lk4+0)*128 + lr+64] = b1.x; Bs[(lk4+1)*128 + lr+64] = b1.y;
        Bs[(lk4+2)*128 + lr+64] = b1.z; Bs[(lk4+3)*128 + lr+64] = b1.w;
        __syncthreads();
        #pragma unroll
        for (int k = 0; k < 16; k++) {
            const ull* ap = (const ull*)&As[k*128 + ty*8];
            ull a_0 = ap[0], a_1 = ap[1], a_2 = ap[2], a_3 = ap[3];
            const float4* bp = (const float4*)&Bs[k*128 + tx*8];
            float4 bA = bp[0], bB = bp[1];
            ull bd[8];
            bd[0]=dup2(bA.x); bd[1]=dup2(bA.y); bd[2]=dup2(bA.z); bd[3]=dup2(bA.w);
            bd[4]=dup2(bB.x); bd[5]=dup2(bB.y); bd[6]=dup2(bB.z); bd[7]=dup2(bB.w);
            #pragma unroll
            for (int n = 0; n < 8; n++) {
                fma2(acc[0][n], a_0, bd[n]);
                fma2(acc[1][n], a_1, bd[n]);
                fma2(acc[2][n], a_2, bd[n]);
                fma2(acc[3][n], a_3, bd[n]);
            }
        }
    }
    const long col0 = (long)bx * 128 + tx * 8;
    const int  r0   = by * 128 + ty * 8;
    #pragma unroll
    for (int mp = 0; mp < 4; mp++) {
        #pragma unroll
        for (int h = 0; h < 2; h++) {
            int r = r0 + mp*2 + h;
            float bias = g_bias[r];
            float o[8];
            #pragma unroll
            for (int n = 0; n < 8; n++) {
                float2 q = unpack2(acc[mp][n]);
                o[n] = (h ? q.y : q.x) + bias;
            }
            float* dst = &g_xp[(long)r * NCOL + col0];
            *(float4*)(dst)     = make_float4(o[0],o[1],o[2],o[3]);
            *(float4*)(dst + 4) = make_float4(o[4],o[5],o[6],o[7]);
        }
    }
}

// ---------------- phase 2: v2 + fast activations + SPLIT h-load ------------
// 128 CTAs = 32 j-groups x 4 b-groups. CTA owns 64 cols (16 j x 4 gates) x 16 b.
// SINGLE change vs R12 (4094us): all 8 h loads issued up front; stash rows
// 0..3, compute k half 1 (k0..k0+31, uses only those rows) while rows 4..7's
// L2 latency drains, then stash 4..7 and compute half 2. SMEM strides and
// gather pattern are EXACTLY v2's (33/17, [0,8,16,24]/[0,4,8,12]).
__global__ __launch_bounds__(NTHR, 1) void lstm_kernel(
    const float* __restrict__ Uf, const float* __restrict__ Ui,
    const float* __restrict__ Uo, const float* __restrict__ Uc,
    const float* __restrict__ c0, float* __restrict__ out)
{
    extern __shared__ float smem[];
    float2* U2 = (float2*)smem;                  // [k*33 + cp], cp in [0,32)
    float2* h2 = (float2*)(smem + 33792);        // [k*17 + b],  b in [0,16)

    const int tid  = threadIdx.x;
    const int jg   = blockIdx.x & 31;            // j-group: 16 hidden cols
    const int bg   = blockIdx.x >> 5;            // b-group: 16 batches
    const int w    = tid >> 5, lane = tid & 31;
    const int cg   = lane & 7, bg2 = lane >> 3;  // compute-role lane split
    const int jl   = tid & 15, bl = tid >> 4;    // epilogue role
    const int lq   = lane & 3, rl = lane >> 2;   // h-loader role

    // ---- fill U2: column-pair packed (cp = gate*8 + p, j = jg*16 + 2p) ----
    {
        const float* Uw[4] = {Uf, Ui, Uo, Uc};
        for (int idx = tid; idx < 512 * 32; idx += NTHR) {
            int k = idx & 511, cp = idx >> 9;
            const float* Ug = Uw[cp >> 3];
            int j0 = jg * 16 + ((2 * cp) & 15);
            U2[k * 33 + cp] = make_float2(Ug[j0 * NH + k], Ug[(j0 + 1) * NH + k]);
        }
    }
    float creg = c0[(bg * 16 + bl) * NH + jg * 16 + jl];
    long xbase[4];
    #pragma unroll
    for (int g = 0; g < 4; g++)
        xbase[g] = ((long)(g * NH + jg * 16 + jl) << 15) + bg * 16 + bl;

    const float2* ub = U2 + cg;          // lane's 4 col-pairs: cg + 8i
    const float2* hb = h2 + bg2;         // lane's 4 batches:   bg2 + 4q
    float2* stash = h2 + w * 1088;       // warp's own 64-row slice (alias)
    const long obase = (long)(bg * 16 + bl) * 512 + jg * 16 + jl;

    __syncthreads();   // U2 ready

    for (int t = 0; t < SEQ_T; t++) {
        // prefetch xp slice (consumed post-reduction)
        float xg0 = __ldg(&g_xp[xbase[0] + t * 64]);
        float xg1 = __ldg(&g_xp[xbase[1] + t * 64]);
        float xg2 = __ldg(&g_xp[xbase[2] + t * 64]);
        float xg3 = __ldg(&g_xp[xbase[3] + t * 64]);

        // issue ALL h loads for this warp's 64-row slice up front
        const float* hsrc = g_hbuf[t & 1] + bg * 16;
        float4 v[8];
        #pragma unroll
        for (int i = 0; i < 8; i++)
            v[i] = __ldcg((const float4*)(hsrc + (w*64 + i*8 + rl) * 64 + lq * 4));

        // stash rows 0..3 (k0..k0+31), then compute half 1 while 4..7 drain
        #pragma unroll
        for (int i = 0; i < 4; i++) {
            int r = w * 64 + i * 8 + rl;
            float2* d = h2 + r * 17 + lq * 4;
            d[0] = make_float2(v[i].x, v[i].x); d[1] = make_float2(v[i].y, v[i].y);
            d[2] = make_float2(v[i].z, v[i].z); d[3] = make_float2(v[i].w, v[i].w);
        }
        __syncwarp();

        ull acc[4][4];
        #pragma unroll
        for (int i = 0; i < 4; i++)
            #pragma unroll
            for (int q = 0; q < 4; q++) acc[i][q] = 0ull;
        const int k0 = w * 64;
        #pragma unroll 4
        for (int k = k0; k < k0 + 32; k++) {
            const ull* up = (const ull*)(ub + k * 33);
            ull u0 = up[0], u1 = up[8], u2 = up[16], u3 = up[24];
            const ull* hp = (const ull*)(hb + k * 17);
            ull p0 = hp[0], p1 = hp[4], p2 = hp[8], p3 = hp[12];
            fma2(acc[0][0], u0, p0); fma2(acc[1][0], u1, p0);
            fma2(acc[2][0], u2, p0); fma2(acc[3][0], u3, p0);
            fma2(acc[0][1], u0, p1); fma2(acc[1][1], u1, p1);
            fma2(acc[2][1], u2, p1); fma2(acc[3][1], u3, p1);
            fma2(acc[0][2], u0, p2); fma2(acc[1][2], u1, p2);
            fma2(acc[2][2], u2, p2); fma2(acc[3][2], u3, p2);
            fma2(acc[0][3], u0, p3); fma2(acc[1][3], u1, p3);
            fma2(acc[2][3], u2, p3); fma2(acc[3][3], u3, p3);
        }

        // stash rows 4..7, compute half 2
        #pragma unroll
        for (int i = 4; i < 8; i++) {
            int r = w * 64 + i * 8 + rl;
            float2* d = h2 + r * 17 + lq * 4;
            d[0] = make_float2(v[i].x, v[i].x); d[1] = make_float2(v[i].y, v[i].y);
            d[2] = make_float2(v[i].z, v[i].z); d[3] = make_float2(v[i].w, v[i].w);
        }
        __syncwarp();
        #pragma unroll 4
        for (int k = k0 + 32; k < k0 + 64; k++) {
            const ull* up = (const ull*)(ub + k * 33);
            ull u0 = up[0], u1 = up[8], u2 = up[16], u3 = up[24];
            const ull* hp = (const ull*)(hb + k * 17);
            ull p0 = hp[0], p1 = hp[4], p2 = hp[8], p3 = hp[12];
            fma2(acc[0][0], u0, p0); fma2(acc[1][0], u1, p0);
            fma2(acc[2][0], u2, p0); fma2(acc[3][0], u3, p0);
            fma2(acc[0][1], u0, p1); fma2(acc[1][1], u1, p1);
            fma2(acc[2][1], u2, p1); fma2(acc[3][1], u3, p1);
            fma2(acc[0][2], u0, p2); fma2(acc[1][2], u1, p2);
            fma2(acc[2][2], u2, p2); fma2(acc[3][2], u3, p2);
            fma2(acc[0][3], u0, p3); fma2(acc[1][3], u1, p3);
            fma2(acc[2][3], u2, p3); fma2(acc[3][3], u3, p3);
        }
        __syncwarp();
        // stash partials into this warp's (now dead) h2 slice
        #pragma unroll
        for (int i = 0; i < 4; i++)
            #pragma unroll
            for (int q = 0; q < 4; q++)
                *(ull*)&stash[(cg + 8 * i) * 17 + bg2 + 4 * q] = acc[i][q];
        __syncthreads();

        // reduce 8 partials + activations; thread owns (jl, bl)
        float p[4];
        #pragma unroll
        for (int g = 0; g < 4; g++) {
            int c = g * 16 + jl, cp = c >> 1, hf = c & 1;
            float s = 0.f;
            #pragma unroll
            for (int ww = 0; ww < 8; ww++)
                s += ((const float*)(h2 + ww * 1088 + cp * 17 + bl))[hf];
            p[g] = s;
        }
        p[0] += xg0; p[1] += xg1; p[2] += xg2; p[3] += xg3;
        float fg = fsig(p[0]);
        float ig = fsig(p[1]);
        float og = fsig(p[2]);
        float gg = ftanh(p[3]);
        creg = fg * creg + ig * gg;
        float hv = og * ftanh(creg);

        g_hbuf[(t + 1) & 1][(jg * 16 + jl) * 64 + bg * 16 + bl] = hv;

        __syncthreads();   // all h writes issued (cta-scope ordering)
        if (t < SEQ_T - 1) {
            if (tid == 0) {                 // gpu-scope release by one thread
                __threadfence();            // cumulative over the bar above
                atomicAdd(&g_bar[t * 4 + bg], 1u);
            }
        }

        // h_seq store (coalesced: jl fast), overlaps the barrier wait
        out[(long)t * 32768 + obase] = hv;
        if (t == SEQ_T - 1) {
            out[HSEQ_ELEMS + obase] = hv;
            out[HSEQ_ELEMS + 32768 + obase] = creg;
        } else {
            if (tid == 0) {
                volatile unsigned* bp_ = &g_bar[t * 4 + bg];
                while (*bp_ < 32u) { }
                __threadfence();            // acquire
            }
            __syncthreads();                // release barrier result + h2 reuse
        }
    }
}

// ---------------- launch ----------------------------------------------------
extern "C" void kernel_launch(void* const* d_in, const int* in_sizes, int n_in,
                              void* d_out, int out_size)
{
    const float* x    = (const float*)d_in[0];
    const float* h0   = (const float*)d_in[1];
    const float* c0   = (const float*)d_in[2];
    const float* Wf_w = (const float*)d_in[3];
    const float* Wf_b = (const float*)d_in[4];
    const float* Uf_w = (const float*)d_in[5];
    const float* Uf_b = (const float*)d_in[6];
    const float* Wi_w = (const float*)d_in[7];
    const float* Wi_b = (const float*)d_in[8];
    const float* Ui_w = (const float*)d_in[9];
    const float* Ui_b = (const float*)d_in[10];
    const float* Wo_w = (const float*)d_in[11];
    const float* Wo_b = (const float*)d_in[12];
    const float* Uo_w = (const float*)d_in[13];
    const float* Uo_b = (const float*)d_in[14];
    const float* Wc_w = (const float*)d_in[15];
    const float* Wc_b = (const float*)d_in[16];
    const float* Uc_w = (const float*)d_in[17];
    const float* Uc_b = (const float*)d_in[18];
    float* out = (float*)d_out;

    cudaFuncSetAttribute(lstm_kernel,
        cudaFuncAttributeMaxDynamicSharedMemorySize, LSTM_SMEM);

    init_kernel<<<128, 256>>>(h0, Wf_b, Uf_b, Wi_b, Ui_b,
                              Wo_b, Uo_b, Wc_b, Uc_b);

    dim3 g1(NCOL / 128, NROW / 128);   // (256, 16)
    gemm_xw<<<g1, 256>>>(x, Wf_w, Wi_w, Wo_w, Wc_w);

    lstm_kernel<<<NCTA, NTHR, LSTM_SMEM>>>(Uf_w, Ui_w, Uo_w, Uc_w, c0, out);
}

// round 15
// speedup vs baseline: 1.0191x; 1.0191x over previous
#include <cuda_runtime.h>

typedef unsigned long long ull;

#define SEQ_T 512
#define NB    64
#define NIN   256
#define NH    512
#define NROW  2048                    // 4 gates * NH rows
#define NCOL  32768                   // SEQ_T * NB
#define NCTA  128                     // 32 j-groups x 4 b-groups
#define NTHR  256
#define HSEQ_ELEMS (512L*64*512)      // 16777216
// lstm smem: U2 (512k x 33 f2) 135168B + h2 (512k x 17 f2) 69632B
#define LSTM_SMEM (135168 + 69632)

// ---------------- device scratch (static: no allocations allowed) ----------
__device__ float    g_xp[(long)NROW * NCOL];   // [gate*512+j][t*64+b]
__device__ float    g_hbuf[2][NH * NB];        // [j][b] layout, double buffered
__device__ float    g_bias[NROW];              // Wb + Ub folded
__device__ unsigned g_bar[SEQ_T * 4];          // per-(step, b-group) barrier slots

// ---------------- f32x2 helpers (packed FFMA2 = 2x fp32 throughput) --------
__device__ __forceinline__ void fma2(ull &d, ull a, ull b){
    asm("fma.rn.f32x2 %0, %1, %2, %0;" : "+l"(d) : "l"(a), "l"(b));
}
__device__ __forceinline__ ull dup2(float v){
    ull r; asm("mov.b64 %0, {%1, %1};" : "=l"(r) : "f"(v)); return r;
}
__device__ __forceinline__ float2 unpack2(ull v){
    float2 r; asm("mov.b64 {%0, %1}, %2;" : "=f"(r.x), "=f"(r.y) : "l"(v)); return r;
}
// fast sigmoid / tanh via MUFU (__expf + __fdividef); exact limits at +-inf.
// Validated: rel_err 2.8e-7 (threshold 1e-3).
__device__ __forceinline__ float fsig(float x){
    return __fdividef(1.f, 1.f + __expf(-x));
}
__device__ __forceinline__ float ftanh(float x){
    return 1.f - __fdividef(2.f, __expf(2.f * x) + 1.f);
}

// ---------------- init: h0 -> hbuf[0] ([j][b]), fold biases, zero barriers -
__global__ void init_kernel(const float* __restrict__ h0,
    const float* __restrict__ Wfb, const float* __restrict__ Ufb,
    const float* __restrict__ Wib, const float* __restrict__ Uib,
    const float* __restrict__ Wob, const float* __restrict__ Uob,
    const float* __restrict__ Wcb, const float* __restrict__ Ucb)
{
    int i = blockIdx.x * blockDim.x + threadIdx.x;   // 0..32767
    int j = i >> 6, b = i & 63;
    g_hbuf[0][i] = h0[b * NH + j];                   // transpose to [j][b]
    if (i < NROW) {
        int g = i >> 9, jj = i & 511;
        const float* Wb = (g==0)?Wfb:(g==1)?Wib:(g==2)?Wob:Wcb;
        const float* Ub = (g==0)?Ufb:(g==1)?Uib:(g==2)?Uob:Ucb;
        g_bias[i] = Wb[jj] + Ub[jj];
    }
    if (i < SEQ_T * 4) g_bar[i] = 0u;
}

// ---------------- phase 1: xp = W @ x^T + (Wb+Ub), all 4 gates -------------
// SINGLE change this round: minBlocksPerMultiprocessor = 2 (128-reg cap) so a
// sibling CTA hides the per-k-tile bar.sync and tile-load latency bubbles.
// Register audit: acc 64 + bd 16 + a 8 + prefetch 16 + addressing ~15 = ~119.
__global__ __launch_bounds__(256, 2) void gemm_xw(
    const float* __restrict__ x,
    const float* __restrict__ Wf, const float* __restrict__ Wi,
    const float* __restrict__ Wo, const float* __restrict__ Wc)
{
    __shared__ float As[16 * 128];
    __shared__ float Bs[16 * 128];
    const int tid = threadIdx.x;
    const int bx = blockIdx.x, by = blockIdx.y;
    const int g = (by * 128) >> 9;
    const float* Wg = (g==0)?Wf:(g==1)?Wi:(g==2)?Wo:Wc;
    const int rowA0 = (by * 128) & 511;
    const int tx = tid & 15, ty = tid >> 4;
    const int lr = tid >> 2;
    const int lk4 = (tid & 3) * 4;

    ull acc[4][8];
    #pragma unroll
    for (int m = 0; m < 4; m++)
        #pragma unroll
        for (int n = 0; n < 8; n++) acc[m][n] = 0ull;

    for (int kt = 0; kt < NIN; kt += 16) {
        float4 a0 = __ldg((const float4*)&Wg[(rowA0 + lr)      * NIN + kt + lk4]);
        float4 a1 = __ldg((const float4*)&Wg[(rowA0 + lr + 64) * NIN + kt + lk4]);
        float4 b0 = __ldg((const float4*)&x[((long)bx*128 + lr)      * NIN + kt + lk4]);
        float4 b1 = __ldg((const float4*)&x[((long)bx*128 + lr + 64) * NIN + kt + lk4]);
        __syncthreads();
        As[(lk4+0)*128 + lr] = a0.x; As[(lk4+1)*128 + lr] = a0.y;
        As[(lk4+2)*128 + lr] = a0.z; As[(lk4+3)*128 + lr] = a0.w;
        As[(lk4+0)*128 + lr+64] = a1.x; As[(lk4+1)*128 + lr+64] = a1.y;
        As[(lk4+2)*128 + lr+64] = a1.z; As[(lk4+3)*128 + lr+64] = a1.w;
        Bs[(lk4+0)*128 + lr] = b0.x; Bs[(lk4+1)*128 + lr] = b0.y;
        Bs[(lk4+2)*128 + lr] = b0.z; Bs[(lk4+3)*128 + lr] = b0.w;
        Bs[(lk4+0)*128 + lr+64] = b1.x; Bs[(lk4+1)*128 + lr+64] = b1.y;
        Bs[(lk4+2)*128 + lr+64] = b1.z; Bs[(lk4+3)*128 + lr+64] = b1.w;
        __syncthreads();
        #pragma unroll
        for (int k = 0; k < 16; k++) {
            const ull* ap = (const ull*)&As[k*128 + ty*8];
            ull a_0 = ap[0], a_1 = ap[1], a_2 = ap[2], a_3 = ap[3];
            const float4* bp = (const float4*)&Bs[k*128 + tx*8];
            float4 bA = bp[0], bB = bp[1];
            ull bd[8];
            bd[0]=dup2(bA.x); bd[1]=dup2(bA.y); bd[2]=dup2(bA.z); bd[3]=dup2(bA.w);
            bd[4]=dup2(bB.x); bd[5]=dup2(bB.y); bd[6]=dup2(bB.z); bd[7]=dup2(bB.w);
            #pragma unroll
            for (int n = 0; n < 8; n++) {
                fma2(acc[0][n], a_0, bd[n]);
                fma2(acc[1][n], a_1, bd[n]);
                fma2(acc[2][n], a_2, bd[n]);
                fma2(acc[3][n], a_3, bd[n]);
            }
        }
    }
    const long col0 = (long)bx * 128 + tx * 8;
    const int  r0   = by * 128 + ty * 8;
    #pragma unroll
    for (int mp = 0; mp < 4; mp++) {
        #pragma unroll
        for (int h = 0; h < 2; h++) {
            int r = r0 + mp*2 + h;
            float bias = g_bias[r];
            float o[8];
            #pragma unroll
            for (int n = 0; n < 8; n++) {
                float2 q = unpack2(acc[mp][n]);
                o[n] = (h ? q.y : q.x) + bias;
            }
            float* dst = &g_xp[(long)r * NCOL + col0];
            *(float4*)(dst)     = make_float4(o[0],o[1],o[2],o[3]);
            *(float4*)(dst + 4) = make_float4(o[4],o[5],o[6],o[7]);
        }
    }
}

// ---------------- phase 2: EXACT R12 (proven 4094us) -----------------------
// 128 CTAs = 32 j-groups x 4 b-groups. CTA owns 64 cols (16 j x 4 gates) x 16 b.
// v2 k-loop (33/17 strides, interleaved ldcg+stash), fast activations,
// counter barrier with tid0 fence/spin. Byte-identical to the 4094us run.
__global__ __launch_bounds__(NTHR, 1) void lstm_kernel(
    const float* __restrict__ Uf, const float* __restrict__ Ui,
    const float* __restrict__ Uo, const float* __restrict__ Uc,
    const float* __restrict__ c0, float* __restrict__ out)
{
    extern __shared__ float smem[];
    float2* U2 = (float2*)smem;                  // [k*33 + cp], cp in [0,32)
    float2* h2 = (float2*)(smem + 33792);        // [k*17 + b],  b in [0,16)

    const int tid  = threadIdx.x;
    const int jg   = blockIdx.x & 31;            // j-group: 16 hidden cols
    const int bg   = blockIdx.x >> 5;            // b-group: 16 batches
    const int w    = tid >> 5, lane = tid & 31;
    const int cg   = lane & 7, bg2 = lane >> 3;  // compute-role lane split
    const int jl   = tid & 15, bl = tid >> 4;    // epilogue role
    const int lq   = lane & 3, rl = lane >> 2;   // h-loader role

    // ---- fill U2: column-pair packed (cp = gate*8 + p, j = jg*16 + 2p) ----
    {
        const float* Uw[4] = {Uf, Ui, Uo, Uc};
        for (int idx = tid; idx < 512 * 32; idx += NTHR) {
            int k = idx & 511, cp = idx >> 9;
            const float* Ug = Uw[cp >> 3];
            int j0 = jg * 16 + ((2 * cp) & 15);
            U2[k * 33 + cp] = make_float2(Ug[j0 * NH + k], Ug[(j0 + 1) * NH + k]);
        }
    }
    float creg = c0[(bg * 16 + bl) * NH + jg * 16 + jl];
    long xbase[4];
    #pragma unroll
    for (int g = 0; g < 4; g++)
        xbase[g] = ((long)(g * NH + jg * 16 + jl) << 15) + bg * 16 + bl;

    const float2* ub = U2 + cg;          // lane's 4 col-pairs: cg + 8i
    const float2* hb = h2 + bg2;         // lane's 4 batches:   bg2 + 4q
    float2* stash = h2 + w * 1088;       // warp's own 64-row slice (alias)
    const long obase = (long)(bg * 16 + bl) * 512 + jg * 16 + jl;

    __syncthreads();   // U2 ready

    for (int t = 0; t < SEQ_T; t++) {
        // prefetch xp slice (consumed post-reduction)
        float xg0 = __ldg(&g_xp[xbase[0] + t * 64]);
        float xg1 = __ldg(&g_xp[xbase[1] + t * 64]);
        float xg2 = __ldg(&g_xp[xbase[2] + t * 64]);
        float xg3 = __ldg(&g_xp[xbase[3] + t * 64]);

        // each warp loads ONLY its own 64-row k slice of h (32KB/CTA total),
        // dup-packing into f32x2 — no block sync needed before compute
        const float* hsrc = g_hbuf[t & 1] + bg * 16;
        #pragma unroll
        for (int i = 0; i < 8; i++) {
            int r = w * 64 + i * 8 + rl;
            float4 v = __ldcg((const float4*)(hsrc + r * 64 + lq * 4));
            float2* d = h2 + r * 17 + lq * 4;
            d[0] = make_float2(v.x, v.x); d[1] = make_float2(v.y, v.y);
            d[2] = make_float2(v.z, v.z); d[3] = make_float2(v.w, v.w);
        }
        __syncwarp();

        // split-k partial GEMM: 4 col-pairs x 4 batches per lane over 64 k
        ull acc[4][4];
        #pragma unroll
        for (int i = 0; i < 4; i++)
            #pragma unroll
            for (int q = 0; q < 4; q++) acc[i][q] = 0ull;
        const int k0 = w * 64;
        #pragma unroll 4
        for (int k = k0; k < k0 + 64; k++) {
            const ull* up = (const ull*)(ub + k * 33);
            ull u0 = up[0], u1 = up[8], u2 = up[16], u3 = up[24];
            const ull* hp = (const ull*)(hb + k * 17);
            ull p0 = hp[0], p1 = hp[4], p2 = hp[8], p3 = hp[12];
            fma2(acc[0][0], u0, p0); fma2(acc[1][0], u1, p0);
            fma2(acc[2][0], u2, p0); fma2(acc[3][0], u3, p0);
            fma2(acc[0][1], u0, p1); fma2(acc[1][1], u1, p1);
            fma2(acc[2][1], u2, p1); fma2(acc[3][1], u3, p1);
            fma2(acc[0][2], u0, p2); fma2(acc[1][2], u1, p2);
            fma2(acc[2][2], u2, p2); fma2(acc[3][2], u3, p2);
            fma2(acc[0][3], u0, p3); fma2(acc[1][3], u1, p3);
            fma2(acc[2][3], u2, p3); fma2(acc[3][3], u3, p3);
        }
        __syncwarp();
        // stash partials into this warp's (now dead) h2 slice
        #pragma unroll
        for (int i = 0; i < 4; i++)
            #pragma unroll
            for (int q = 0; q < 4; q++)
                *(ull*)&stash[(cg + 8 * i) * 17 + bg2 + 4 * q] = acc[i][q];
        __syncthreads();

        // reduce 8 partials + activations; thread owns (jl, bl)
        float p[4];
        #pragma unroll
        for (int g = 0; g < 4; g++) {
            int c = g * 16 + jl, cp = c >> 1, hf = c & 1;
            float s = 0.f;
            #pragma unroll
            for (int ww = 0; ww < 8; ww++)
                s += ((const float*)(h2 + ww * 1088 + cp * 17 + bl))[hf];
            p[g] = s;
        }
        p[0] += xg0; p[1] += xg1; p[2] += xg2; p[3] += xg3;
        float fg = fsig(p[0]);
        float ig = fsig(p[1]);
        float og = fsig(p[2]);
        float gg = ftanh(p[3]);
        creg = fg * creg + ig * gg;
        float hv = og * ftanh(creg);

        g_hbuf[(t + 1) & 1][(jg * 16 + jl) * 64 + bg * 16 + bl] = hv;

        __syncthreads();   // all h writes issued (cta-scope ordering)
        if (t < SEQ_T - 1) {
            if (tid == 0) {                 // gpu-scope release by one thread
                __threadfence();            // cumulative over the bar above
                atomicAdd(&g_bar[t * 4 + bg], 1u);
            }
        }

        // h_seq store (coalesced: jl fast), overlaps the barrier wait
        out[(long)t * 32768 + obase] = hv;
        if (t == SEQ_T - 1) {
            out[HSEQ_ELEMS + obase] = hv;
            out[HSEQ_ELEMS + 32768 + obase] = creg;
        } else {
            if (tid == 0) {
                volatile unsigned* bp_ = &g_bar[t * 4 + bg];
                while (*bp_ < 32u) { }
                __threadfence();            // acquire
            }
            __syncthreads();                // release barrier result + h2 reuse
        }
    }
}

// ---------------- launch ----------------------------------------------------
extern "C" void kernel_launch(void* const* d_in, const int* in_sizes, int n_in,
                              void* d_out, int out_size)
{
    const float* x    = (const float*)d_in[0];
    const float* h0   = (const float*)d_in[1];
    const float* c0   = (const float*)d_in[2];
    const float* Wf_w = (const float*)d_in[3];
    const float* Wf_b = (const float*)d_in[4];
    const float* Uf_w = (const float*)d_in[5];
    const float* Uf_b = (const float*)d_in[6];
    const float* Wi_w = (const float*)d_in[7];
    const float* Wi_b = (const float*)d_in[8];
    const float* Ui_w = (const float*)d_in[9];
    const float* Ui_b = (const float*)d_in[10];
    const float* Wo_w = (const float*)d_in[11];
    const float* Wo_b = (const float*)d_in[12];
    const float* Uo_w = (const float*)d_in[13];
    const float* Uo_b = (const float*)d_in[14];
    const float* Wc_w = (const float*)d_in[15];
    const float* Wc_b = (const float*)d_in[16];
    const float* Uc_w = (const float*)d_in[17];
    const float* Uc_b = (const float*)d_in[18];
    float* out = (float*)d_out;

    cudaFuncSetAttribute(lstm_kernel,
        cudaFuncAttributeMaxDynamicSharedMemorySize, LSTM_SMEM);

    init_kernel<<<128, 256>>>(h0, Wf_b, Uf_b, Wi_b, Ui_b,
                              Wo_b, Uo_b, Wc_b, Uc_b);

    dim3 g1(NCOL / 128, NROW / 128);   // (256, 16)
    gemm_xw<<<g1, 256>>>(x, Wf_w, Wi_w, Wo_w, Wc_w);

    lstm_kernel<<<NCTA, NTHR, LSTM_SMEM>>>(Uf_w, Ui_w, Uo_w, Uc_w, c0, out);
}